// round 3
// baseline (speedup 1.0000x reference)
#include <cuda_runtime.h>

#define NROWS 65536
#define DOUT  128
#define DLAT  64
#define DZ    64

#define NBLOCKS 592               // 4 * 148 SMs -> one balanced wave
#define TPB     256
#define T_TOT   (NBLOCKS * TPB)   // 151552, multiple of 16

#define N_OUT4  (NROWS * DOUT / 4)   // 2097152 = 13*T_TOT + 126976
#define N_LAT4  (NROWS * DLAT / 4)   // 1048576 = 6*T_TOT + 139264
#define REM_OUT 126976
#define REM_LAT 139264

// Zero-initialized device globals (reset by last block each call -> replay-safe)
__device__ float        g_scal[2];      // [0]=KL elem sum, [1]=recon sq sum
__device__ float        g_col[5][DZ];   // Sz, Szt, Sz2, Szt2, Szp
__device__ unsigned int g_count;

__device__ __forceinline__ void recon_body(const float4& o, const float4& t,
                                           float& b0, float& b1) {
    float d0 = o.x - t.x, d1 = o.y - t.y, d2 = o.z - t.z, d3 = o.w - t.w;
    b0 += d0 * d0 + d1 * d1;
    b1 += d2 * d2 + d3 * d3;
}

__device__ __forceinline__ void klz_body(const float4& lv, const float4& m,
                                         const float4& u, const float4& v,
                                         float& a, float st[5][4]) {
    a += (lv.x - __expf(lv.x) - m.x * m.x + 1.0f);
    a += (lv.y - __expf(lv.y) - m.y * m.y + 1.0f);
    a += (lv.z - __expf(lv.z) - m.z * m.z + 1.0f);
    a += (lv.w - __expf(lv.w) - m.w * m.w + 1.0f);
    st[0][0] += u.x; st[1][0] += v.x; st[2][0] += u.x * u.x; st[3][0] += v.x * v.x; st[4][0] += u.x * v.x;
    st[0][1] += u.y; st[1][1] += v.y; st[2][1] += u.y * u.y; st[3][1] += v.y * v.y; st[4][1] += u.y * v.y;
    st[0][2] += u.z; st[1][2] += v.z; st[2][2] += u.z * u.z; st[3][2] += v.z * v.z; st[4][2] += u.z * v.z;
    st[0][3] += u.w; st[1][3] += v.w; st[2][3] += u.w * u.w; st[3][3] += v.w * v.w; st[4][3] += u.w * v.w;
}

__global__ void __launch_bounds__(TPB, 4) vde_fused_kernel(
    const float4* __restrict__ target,
    const float4* __restrict__ output,
    const float4* __restrict__ mean,
    const float4* __restrict__ logv,
    const float4* __restrict__ z,
    const float4* __restrict__ zt,
    float* __restrict__ out)
{
    const int tid  = blockIdx.x * TPB + threadIdx.x;
    const int lane = threadIdx.x & 31;
    const int warp = threadIdx.x >> 5;

    // ================= merged KL + z-stats loop: 4 independent LDG.128/body ====
    float a = 0.0f;
    float st[5][4] = {{0}};
    {
        int i = tid;
        #pragma unroll
        for (int k = 0; k < 6; k++) {
            float4 lv = __ldcs(logv + i);
            float4 m  = __ldcs(mean + i);
            float4 u  = __ldcs(z    + i);
            float4 v  = __ldcs(zt   + i);
            klz_body(lv, m, u, v, a, st);
            i += T_TOT;
        }
        if (tid < REM_LAT) {
            float4 lv = __ldcs(logv + i);
            float4 m  = __ldcs(mean + i);
            float4 u  = __ldcs(z    + i);
            float4 v  = __ldcs(zt   + i);
            klz_body(lv, m, u, v, a, st);
        }
    }

    // ================= reconstruction: 13 + tail, pair-batched =================
    float b0 = 0.0f, b1 = 0.0f;
    {
        int i = tid;
        #pragma unroll
        for (int k = 0; k < 6; k++) {
            float4 o0 = __ldcs(output + i);
            float4 t0 = __ldcs(target + i);
            float4 o1 = __ldcs(output + i + T_TOT);
            float4 t1 = __ldcs(target + i + T_TOT);
            recon_body(o0, t0, b0, b1);
            recon_body(o1, t1, b0, b1);
            i += 2 * T_TOT;
        }
        {   // 13th iteration
            float4 o = __ldcs(output + i);
            float4 t = __ldcs(target + i);
            recon_body(o, t, b0, b1);
            i += T_TOT;
        }
        if (tid < REM_OUT) {
            float4 o = __ldcs(output + i);
            float4 t = __ldcs(target + i);
            recon_body(o, t, b0, b1);
        }
    }
    float b = b0 + b1;

    // ---- warp combine: lanes l and l+16 own the same columns ----
    #pragma unroll
    for (int s = 0; s < 5; s++)
        #pragma unroll
        for (int c = 0; c < 4; c++)
            st[s][c] += __shfl_xor_sync(0xFFFFFFFFu, st[s][c], 16);

    #pragma unroll
    for (int off = 16; off; off >>= 1) {
        a += __shfl_down_sync(0xFFFFFFFFu, a, off);
        b += __shfl_down_sync(0xFFFFFFFFu, b, off);
    }

    // ---- block combine via plain shared stores ----
    __shared__ float s_part[8][320];
    __shared__ float s_ab[8][2];

    if (lane < 16) {
        #pragma unroll
        for (int s = 0; s < 5; s++)
            #pragma unroll
            for (int c = 0; c < 4; c++)
                s_part[warp][(s * 4 + c) * 16 + lane] = st[s][c];
    }
    if (lane == 0) { s_ab[warp][0] = a; s_ab[warp][1] = b; }
    __syncthreads();

    for (int idx = threadIdx.x; idx < 320; idx += TPB) {
        float v = 0.0f;
        #pragma unroll
        for (int w = 0; w < 8; w++) v += s_part[w][idx];
        int s   = idx >> 6;
        int rem = idx & 63;
        int c   = rem >> 4;
        int l   = rem & 15;
        atomicAdd(&g_col[s][l * 4 + c], v);
    }
    if (threadIdx.x == 0) {
        float ta = 0.0f, tb = 0.0f;
        #pragma unroll
        for (int w = 0; w < 8; w++) { ta += s_ab[w][0]; tb += s_ab[w][1]; }
        atomicAdd(&g_scal[0], ta);
        atomicAdd(&g_scal[1], tb);
    }

    // ---- last block finalizes + resets ----
    __shared__ unsigned int s_rank;
    __threadfence();
    __syncthreads();
    if (threadIdx.x == 0) s_rank = atomicAdd(&g_count, 1u);
    __syncthreads();
    if (s_rank != NBLOCKS - 1) return;

    __threadfence();

    __shared__ float sc[2], ss[2];
    if (threadIdx.x < DZ) {
        const int d = threadIdx.x;
        const float invN = 1.0f / (float)NROWS;
        float Sz   = *((volatile float*)&g_col[0][d]);
        float Szt  = *((volatile float*)&g_col[1][d]);
        float Sz2  = *((volatile float*)&g_col[2][d]);
        float Szt2 = *((volatile float*)&g_col[3][d]);
        float Szp  = *((volatile float*)&g_col[4][d]);

        float mu = Sz * invN, nu = Szt * invN;
        float cov  = Szp * invN - mu * nu;
        float vart = (Sz2  - (float)NROWS * mu * mu) / (float)(NROWS - 1);
        float varu = (Szt2 - (float)NROWS * nu * nu) / (float)(NROWS - 1);
        float sp = sqrtf(fmaxf(vart * varu, 0.0f));

        #pragma unroll
        for (int off = 16; off; off >>= 1) {
            cov += __shfl_down_sync(0xFFFFFFFFu, cov, off);
            sp  += __shfl_down_sync(0xFFFFFFFFu, sp,  off);
        }
        if (lane == 0) { sc[warp] = cov; ss[warp] = sp; }
    }
    __syncthreads();

    if (threadIdx.x == 0) {
        const float invN = 1.0f / (float)NROWS;
        float num = sc[0] + sc[1];
        float dot = ss[0] + ss[1];
        float kl    = -0.5f * (*((volatile float*)&g_scal[0])) * invN;
        float recon = (*((volatile float*)&g_scal[1])) / (float)((long long)NROWS * DOUT);
        out[0] = recon + kl - num / dot;
    }
    __syncthreads();

    for (int i = threadIdx.x; i < 5 * DZ; i += TPB) ((float*)g_col)[i] = 0.0f;
    if (threadIdx.x == 0) { g_scal[0] = 0.0f; g_scal[1] = 0.0f; g_count = 0u; }
}

extern "C" void kernel_launch(void* const* d_in, const int* in_sizes, int n_in,
                              void* d_out, int out_size) {
    (void)in_sizes; (void)n_in; (void)out_size;
    vde_fused_kernel<<<NBLOCKS, TPB>>>(
        (const float4*)d_in[0], (const float4*)d_in[1],
        (const float4*)d_in[2], (const float4*)d_in[3],
        (const float4*)d_in[4], (const float4*)d_in[5],
        (float*)d_out);
}

// round 4
// speedup vs baseline: 1.1231x; 1.1231x over previous
#include <cuda_runtime.h>

#define NROWS 65536
#define DOUT  128
#define DLAT  64
#define DZ    64

#define NSMS    152
#define TPB     256
#define NBLOCKS (NSMS * 6)            // 912, one balanced wave at 6 blocks/SM
#define T_TOT   (NBLOCKS * TPB)       // 233472

#define ROW_STRIDE (T_TOT / 64)       // 3648 rows per step
#define FULL_ROW_ITERS 17             // 65536 = 17*3648 + 3520
#define ROW_TAIL 3520

#define N_OUT4  (NROWS * DOUT / 4)    // 2097152 = 8*T_TOT + 229376
#define OUT_TAIL 229376

// Zero-initialized device globals (reset by last block each call -> replay-safe)
__device__ float        g_scal[2];      // [0]=KL elem sum, [1]=recon sq sum
__device__ float        g_col[5][DZ];   // Sz, Szt, Sz2, Szt2, Szp
__device__ unsigned int g_count;

__global__ void __launch_bounds__(TPB, 6) vde_fused_kernel(
    const float*  __restrict__ target,
    const float*  __restrict__ output,
    const float*  __restrict__ mean,
    const float*  __restrict__ logv,
    const float*  __restrict__ z,
    const float*  __restrict__ zt,
    float* __restrict__ out)
{
    const int tid  = blockIdx.x * TPB + threadIdx.x;
    const int lane = threadIdx.x & 31;
    const int warp = threadIdx.x >> 5;
    const int col  = tid & 63;          // owned latent column
    const int rb   = tid >> 6;          // starting row, 0..3647

    // ============ unified latent loop: KL + z column stats, scalar loads ======
    float a = 0.0f;
    float s1 = 0.0f, s2 = 0.0f, s3 = 0.0f, s4 = 0.0f, s5 = 0.0f;
    {
        int row = rb;
        // 17 full iterations = 4 batches of 4 + 1
        #pragma unroll
        for (int bb = 0; bb < 4; bb++) {
            float lv[4], m[4], u[4], v[4];
            #pragma unroll
            for (int j = 0; j < 4; j++) {
                int idx = (row + j * ROW_STRIDE) * 64 + col;
                lv[j] = __ldcs(logv + idx);
                m[j]  = __ldcs(mean + idx);
                u[j]  = __ldcs(z    + idx);
                v[j]  = __ldcs(zt   + idx);
            }
            #pragma unroll
            for (int j = 0; j < 4; j++) {
                a  += lv[j] - __expf(lv[j]) - m[j] * m[j] + 1.0f;
                s1 += u[j];        s2 += v[j];
                s3 += u[j] * u[j]; s4 += v[j] * v[j];
                s5 += u[j] * v[j];
            }
            row += 4 * ROW_STRIDE;
        }
        {   // iteration 16
            int idx = row * 64 + col;
            float lv = __ldcs(logv + idx), m = __ldcs(mean + idx);
            float u  = __ldcs(z + idx),    v = __ldcs(zt + idx);
            a  += lv - __expf(lv) - m * m + 1.0f;
            s1 += u; s2 += v; s3 += u * u; s4 += v * v; s5 += u * v;
            row += ROW_STRIDE;
        }
        if (rb < ROW_TAIL) {   // iteration 17
            int idx = row * 64 + col;
            float lv = __ldcs(logv + idx), m = __ldcs(mean + idx);
            float u  = __ldcs(z + idx),    v = __ldcs(zt + idx);
            a  += lv - __expf(lv) - m * m + 1.0f;
            s1 += u; s2 += v; s3 += u * u; s4 += v * v; s5 += u * v;
        }
    }

    // ============ reconstruction: float4, 8 full + tail ========================
    float b0 = 0.0f, b1 = 0.0f;
    {
        const float4* o4 = (const float4*)output;
        const float4* t4 = (const float4*)target;
        int i = tid;
        #pragma unroll
        for (int k = 0; k < 4; k++) {
            float4 oa = __ldcs(o4 + i),         ta = __ldcs(t4 + i);
            float4 ob = __ldcs(o4 + i + T_TOT), tb = __ldcs(t4 + i + T_TOT);
            float d0 = oa.x - ta.x, d1 = oa.y - ta.y, d2 = oa.z - ta.z, d3 = oa.w - ta.w;
            b0 += d0 * d0 + d1 * d1; b1 += d2 * d2 + d3 * d3;
            float e0 = ob.x - tb.x, e1 = ob.y - tb.y, e2 = ob.z - tb.z, e3 = ob.w - tb.w;
            b0 += e0 * e0 + e1 * e1; b1 += e2 * e2 + e3 * e3;
            i += 2 * T_TOT;
        }
        if (tid < OUT_TAIL) {
            float4 oa = __ldcs(o4 + i), ta = __ldcs(t4 + i);
            float d0 = oa.x - ta.x, d1 = oa.y - ta.y, d2 = oa.z - ta.z, d3 = oa.w - ta.w;
            b0 += d0 * d0 + d1 * d1; b1 += d2 * d2 + d3 * d3;
        }
    }
    float b = b0 + b1;

    // ============ block combine ================================================
    __shared__ float s_col[5][DZ];
    __shared__ float s_ab[2];
    for (int i = threadIdx.x; i < 5 * DZ; i += TPB) ((float*)s_col)[i] = 0.0f;
    if (threadIdx.x < 2) s_ab[threadIdx.x] = 0.0f;
    __syncthreads();

    // 4 threads per column per block -> trivial contention
    atomicAdd(&s_col[0][col], s1);
    atomicAdd(&s_col[1][col], s2);
    atomicAdd(&s_col[2][col], s3);
    atomicAdd(&s_col[3][col], s4);
    atomicAdd(&s_col[4][col], s5);

    #pragma unroll
    for (int off = 16; off; off >>= 1) {
        a += __shfl_down_sync(0xFFFFFFFFu, a, off);
        b += __shfl_down_sync(0xFFFFFFFFu, b, off);
    }
    if (lane == 0) { atomicAdd(&s_ab[0], a); atomicAdd(&s_ab[1], b); }
    __syncthreads();

    for (int i = threadIdx.x; i < 5 * DZ; i += TPB)
        atomicAdd(&((float*)g_col)[i], ((float*)s_col)[i]);
    if (threadIdx.x < 2)
        atomicAdd(&g_scal[threadIdx.x], s_ab[threadIdx.x]);

    // ============ last block finalizes + resets ================================
    __shared__ unsigned int s_rank;
    __threadfence();
    __syncthreads();
    if (threadIdx.x == 0) s_rank = atomicAdd(&g_count, 1u);
    __syncthreads();
    if (s_rank != NBLOCKS - 1) return;

    __threadfence();

    __shared__ float sc[2], ss[2];
    if (threadIdx.x < DZ) {
        const int d = threadIdx.x;
        const float invN = 1.0f / (float)NROWS;
        float Sz   = *((volatile float*)&g_col[0][d]);
        float Szt  = *((volatile float*)&g_col[1][d]);
        float Sz2  = *((volatile float*)&g_col[2][d]);
        float Szt2 = *((volatile float*)&g_col[3][d]);
        float Szp  = *((volatile float*)&g_col[4][d]);

        float mu = Sz * invN, nu = Szt * invN;
        float cov  = Szp * invN - mu * nu;
        float vart = (Sz2  - (float)NROWS * mu * mu) / (float)(NROWS - 1);
        float varu = (Szt2 - (float)NROWS * nu * nu) / (float)(NROWS - 1);
        float sp = sqrtf(fmaxf(vart * varu, 0.0f));

        #pragma unroll
        for (int off = 16; off; off >>= 1) {
            cov += __shfl_down_sync(0xFFFFFFFFu, cov, off);
            sp  += __shfl_down_sync(0xFFFFFFFFu, sp,  off);
        }
        if (lane == 0) { sc[warp] = cov; ss[warp] = sp; }
    }
    __syncthreads();

    if (threadIdx.x == 0) {
        const float invN = 1.0f / (float)NROWS;
        float num = sc[0] + sc[1];
        float dot = ss[0] + ss[1];
        float kl    = -0.5f * (*((volatile float*)&g_scal[0])) * invN;
        float recon = (*((volatile float*)&g_scal[1])) / (float)((long long)NROWS * DOUT);
        out[0] = recon + kl - num / dot;
    }
    __syncthreads();

    for (int i = threadIdx.x; i < 5 * DZ; i += TPB) ((float*)g_col)[i] = 0.0f;
    if (threadIdx.x == 0) { g_scal[0] = 0.0f; g_scal[1] = 0.0f; g_count = 0u; }
}

extern "C" void kernel_launch(void* const* d_in, const int* in_sizes, int n_in,
                              void* d_out, int out_size) {
    (void)in_sizes; (void)n_in; (void)out_size;
    vde_fused_kernel<<<NBLOCKS, TPB>>>(
        (const float*)d_in[0], (const float*)d_in[1],
        (const float*)d_in[2], (const float*)d_in[3],
        (const float*)d_in[4], (const float*)d_in[5],
        (float*)d_out);
}